// round 1
// baseline (speedup 1.0000x reference)
#include <cuda_runtime.h>
#include <cstdint>

// Problem constants
#define Bb 4
#define Nn 4096
#define Dd 256
#define Mm (Bb*Nn)   // 16384 rows

// Scratch for Q, K, V projections (allocation-free: __device__ globals)
__device__ float g_Q[Bb*Nn*Dd];
__device__ float g_K[Bb*Nn*Dd];
__device__ float g_V[Bb*Nn*Dd];

// ---------------------------------------------------------------------------
// Kernel 1: fused QKV projection.  out[m][e] = sum_d x[m][d] * W[e][d] + b[e]
// (torch Linear: x @ W^T + b; W row-major [e][d], so both operands d-major)
// Grid: (e-tiles=4, m-tiles=256, proj=3), 256 threads, 64x64 tile, BK=32.
// ---------------------------------------------------------------------------
__global__ __launch_bounds__(256, 1)
void qkv_kernel(const float* __restrict__ x,
                const float* __restrict__ Wq, const float* __restrict__ bq,
                const float* __restrict__ Wk, const float* __restrict__ bk,
                const float* __restrict__ Wv, const float* __restrict__ bv)
{
    const int z = blockIdx.z;
    const float* W    = (z == 0) ? Wq : (z == 1) ? Wk : Wv;
    const float* bias = (z == 0) ? bq : (z == 1) ? bk : bv;
    float* out        = (z == 0) ? g_Q : (z == 1) ? g_K : g_V;

    const int e0 = blockIdx.x * 64;
    const int m0 = blockIdx.y * 64;
    const int t  = threadIdx.x;
    const int tx = t & 15, ty = t >> 4;

    __shared__ float Xs[64][36];   // 64 rows x 32 k + pad4 (stride mult of 4 for float4)
    __shared__ float Ws[64][36];

    float acc[4][4] = {};

    for (int k0 = 0; k0 < Dd; k0 += 32) {
        {
            int row = t >> 3;          // 0..31
            int col = (t & 7) * 4;     // 0..28
            #pragma unroll
            for (int rr = 0; rr < 2; rr++) {
                *(float4*)&Xs[row + rr*32][col] =
                    *(const float4*)&x[(size_t)(m0 + row + rr*32)*Dd + k0 + col];
                *(float4*)&Ws[row + rr*32][col] =
                    *(const float4*)&W[(size_t)(e0 + row + rr*32)*Dd + k0 + col];
            }
        }
        __syncthreads();
        #pragma unroll
        for (int kk = 0; kk < 32; kk += 4) {
            float4 a4[4], b4[4];
            #pragma unroll
            for (int i = 0; i < 4; i++) a4[i] = *(const float4*)&Xs[ty + i*16][kk];
            #pragma unroll
            for (int j = 0; j < 4; j++) b4[j] = *(const float4*)&Ws[tx + j*16][kk];
            #pragma unroll
            for (int i = 0; i < 4; i++)
                #pragma unroll
                for (int j = 0; j < 4; j++)
                    acc[i][j] += a4[i].x*b4[j].x + a4[i].y*b4[j].y
                               + a4[i].z*b4[j].z + a4[i].w*b4[j].w;
        }
        __syncthreads();
    }

    #pragma unroll
    for (int j = 0; j < 4; j++) {
        float bb = bias[e0 + tx + j*16];
        #pragma unroll
        for (int i = 0; i < 4; i++)
            out[(size_t)(m0 + ty + i*16)*Dd + e0 + tx + j*16] = acc[i][j] + bb;
    }
}

// ---------------------------------------------------------------------------
// Kernel 2: flash-style attention, fp32.
// One CTA per (batch, 64-query tile). 256 threads as 16x16.
// Thread owns S/O rows ty*4+i; S cols tx+j*16; O cols jj*64+tx*4+e.
// smem: Qs[64][260] | Ks[64][68] | Ps[64][68] | Vs[64][260]  = 167,936 B
// ---------------------------------------------------------------------------
#define SMEM_FLOATS (64*260 + 64*68 + 64*68 + 64*260)
#define SMEM_BYTES  (SMEM_FLOATS * 4)

__global__ __launch_bounds__(256, 1)
void attn_kernel(const int* __restrict__ mask, float* __restrict__ out)
{
    extern __shared__ float sm[];
    float* Qs = sm;                    // 64 x 260
    float* Ks = Qs + 64*260;           // 64 x 68
    float* Ps = Ks + 64*68;            // 64 x 68
    float* Vs = Ps + 64*68;            // 64 x 260

    const int b  = blockIdx.y;
    const int q0 = blockIdx.x * 64;
    const int t  = threadIdx.x;
    const int tx = t & 15, ty = t >> 4;

    const float scale   = 0.0625f;                      // 1/sqrt(256)
    const float NEG_INF = __int_as_float(0xff800000);

    // Load Q tile (64 x 256) into smem, vectorized & coalesced.
    #pragma unroll
    for (int it = 0; it < 16; it++) {
        int lin = it*1024 + t*4;
        int row = lin >> 8, col = lin & 255;
        *(float4*)&Qs[row*260 + col] =
            *(const float4*)&g_Q[(size_t)(b*Nn + q0 + row)*Dd + col];
    }

    float m_i[4], l_i[4];
    float o[4][4][4] = {};   // [row i][col group jj][elem e]
    #pragma unroll
    for (int i = 0; i < 4; i++) { m_i[i] = NEG_INF; l_i[i] = 0.f; }

    for (int j0 = 0; j0 < Nn; j0 += 64) {
        // ---- S = Q @ K^T for this key tile, K streamed in 64-d chunks ----
        float s[4][4] = {};
        #pragma unroll
        for (int d0 = 0; d0 < Dd; d0 += 64) {
            __syncthreads();   // Ks (and last tile's Ps/Vs reads) safe to overwrite
            #pragma unroll
            for (int rr = 0; rr < 4; rr++) {
                int row = rr*16 + ty;
                int col = tx * 4;
                *(float4*)&Ks[row*68 + col] =
                    *(const float4*)&g_K[(size_t)(b*Nn + j0 + row)*Dd + d0 + col];
            }
            __syncthreads();
            #pragma unroll
            for (int dd = 0; dd < 64; dd += 4) {
                float4 q4[4], k4[4];
                #pragma unroll
                for (int i = 0; i < 4; i++)
                    q4[i] = *(const float4*)&Qs[(ty*4 + i)*260 + d0 + dd];
                #pragma unroll
                for (int j = 0; j < 4; j++)
                    k4[j] = *(const float4*)&Ks[(tx + j*16)*68 + dd];
                #pragma unroll
                for (int i = 0; i < 4; i++)
                    #pragma unroll
                    for (int j = 0; j < 4; j++)
                        s[i][j] += q4[i].x*k4[j].x + q4[i].y*k4[j].y
                                 + q4[i].z*k4[j].z + q4[i].w*k4[j].w;
            }
        }

        // ---- mask (fill BEFORE scaling, matching reference) ----
        #pragma unroll
        for (int i = 0; i < 4; i++) {
            const int* mrow = mask + ((size_t)(b*Nn + q0 + ty*4 + i))*(size_t)Nn + j0;
            #pragma unroll
            for (int j = 0; j < 4; j++) {
                int mv = mrow[tx + j*16];
                s[i][j] = (mv == 0) ? NEG_INF : s[i][j] * scale;
            }
        }

        // ---- online softmax (row stats across the 16-lane tx group) ----
        float p[4][4];
        #pragma unroll
        for (int i = 0; i < 4; i++) {
            float tmax = fmaxf(fmaxf(s[i][0], s[i][1]), fmaxf(s[i][2], s[i][3]));
            #pragma unroll
            for (int w = 8; w >= 1; w >>= 1)
                tmax = fmaxf(tmax, __shfl_xor_sync(0xffffffffu, tmax, w));
            float m_new = fmaxf(m_i[i], tmax);
            float alpha = __expf(m_i[i] - m_new);
            m_i[i] = m_new;
            float psum = 0.f;
            #pragma unroll
            for (int j = 0; j < 4; j++) {
                p[i][j] = __expf(s[i][j] - m_new);
                psum += p[i][j];
            }
            l_i[i] = l_i[i]*alpha + psum;   // lane-partial; reduced once at end
            #pragma unroll
            for (int jj = 0; jj < 4; jj++)
                #pragma unroll
                for (int e = 0; e < 4; e++)
                    o[i][jj][e] *= alpha;
        }

        // ---- stage P, load V tile ----
        #pragma unroll
        for (int i = 0; i < 4; i++)
            #pragma unroll
            for (int j = 0; j < 4; j++)
                Ps[(ty*4 + i)*68 + tx + j*16] = p[i][j];

        #pragma unroll
        for (int it = 0; it < 16; it++) {
            int lin = it*1024 + t*4;
            int row = lin >> 8, col = lin & 255;
            *(float4*)&Vs[row*260 + col] =
                *(const float4*)&g_V[(size_t)(b*Nn + j0 + row)*Dd + col];
        }
        __syncthreads();

        // ---- O += P @ V ----
        #pragma unroll
        for (int k0 = 0; k0 < 64; k0 += 4) {
            float4 p4[4];
            #pragma unroll
            for (int i = 0; i < 4; i++)
                p4[i] = *(const float4*)&Ps[(ty*4 + i)*68 + k0];
            #pragma unroll
            for (int jj = 0; jj < 4; jj++) {
                int cb = jj*64 + tx*4;
                float4 v0 = *(const float4*)&Vs[(k0+0)*260 + cb];
                float4 v1 = *(const float4*)&Vs[(k0+1)*260 + cb];
                float4 v2 = *(const float4*)&Vs[(k0+2)*260 + cb];
                float4 v3 = *(const float4*)&Vs[(k0+3)*260 + cb];
                #pragma unroll
                for (int i = 0; i < 4; i++) {
                    o[i][jj][0] += p4[i].x*v0.x + p4[i].y*v1.x + p4[i].z*v2.x + p4[i].w*v3.x;
                    o[i][jj][1] += p4[i].x*v0.y + p4[i].y*v1.y + p4[i].z*v2.y + p4[i].w*v3.y;
                    o[i][jj][2] += p4[i].x*v0.z + p4[i].y*v1.z + p4[i].z*v2.z + p4[i].w*v3.z;
                    o[i][jj][3] += p4[i].x*v0.w + p4[i].y*v1.w + p4[i].z*v2.w + p4[i].w*v3.w;
                }
            }
        }
        // Next tile's smem overwrites are fenced by the syncs at the top of
        // its d0 loop, which no thread passes before all finish this P@V.
    }

    // ---- finalize: reduce l over the 16-lane group, scale, store ----
    #pragma unroll
    for (int i = 0; i < 4; i++) {
        float l = l_i[i];
        #pragma unroll
        for (int w = 8; w >= 1; w >>= 1)
            l += __shfl_xor_sync(0xffffffffu, l, w);
        float inv = 1.0f / l;
        int q = q0 + ty*4 + i;
        #pragma unroll
        for (int jj = 0; jj < 4; jj++) {
            float4 r;
            r.x = o[i][jj][0]*inv; r.y = o[i][jj][1]*inv;
            r.z = o[i][jj][2]*inv; r.w = o[i][jj][3]*inv;
            *(float4*)&out[(size_t)(b*Nn + q)*Dd + jj*64 + tx*4] = r;
        }
    }
}

// ---------------------------------------------------------------------------
// Launch. Inputs per metadata order: x, mask, Wq, bq, Wk, bk, Wv, bv.
// ---------------------------------------------------------------------------
extern "C" void kernel_launch(void* const* d_in, const int* in_sizes, int n_in,
                              void* d_out, int out_size)
{
    const float* x    = (const float*)d_in[0];
    const int*   mask = (const int*)  d_in[1];
    const float* Wq   = (const float*)d_in[2];
    const float* bq   = (const float*)d_in[3];
    const float* Wk   = (const float*)d_in[4];
    const float* bk   = (const float*)d_in[5];
    const float* Wv   = (const float*)d_in[6];
    const float* bv   = (const float*)d_in[7];
    float* out = (float*)d_out;

    // Host-side attribute set: not a stream op, legal under graph capture,
    // idempotent and deterministic.
    cudaFuncSetAttribute(attn_kernel,
                         cudaFuncAttributeMaxDynamicSharedMemorySize, SMEM_BYTES);

    dim3 g1(Dd/64, Mm/64, 3);          // (4, 256, 3)
    qkv_kernel<<<g1, 256>>>(x, Wq, bq, Wk, bk, Wv, bv);

    dim3 g2(Nn/64, Bb);                // (64, 4)
    attn_kernel<<<g2, 256, SMEM_BYTES>>>(mask, out);
}

// round 2
// speedup vs baseline: 2.2362x; 2.2362x over previous
#include <cuda_runtime.h>
#include <cstdint>

// Problem constants
#define Bb 4
#define Nn 4096
#define Dd 256
#define Mm (Bb*Nn)   // 16384 rows

// Scratch for Q, K, V projections (allocation-free: __device__ globals)
__device__ float g_Q[Bb*Nn*Dd];
__device__ float g_K[Bb*Nn*Dd];
__device__ float g_V[Bb*Nn*Dd];

// ---------------------------------------------------------------------------
// Packed f32x2 helpers (Blackwell FFMA2: 2 fp32 FMAs per instruction)
// ---------------------------------------------------------------------------
__device__ __forceinline__ unsigned long long ffma2(unsigned long long a,
                                                    unsigned long long b,
                                                    unsigned long long c)
{
    unsigned long long d;
    asm("fma.rn.f32x2 %0, %1, %2, %3;" : "=l"(d) : "l"(a), "l"(b), "l"(c));
    return d;
}
__device__ __forceinline__ unsigned long long fmul2(unsigned long long a,
                                                    unsigned long long b)
{
    unsigned long long d;
    asm("mul.rn.f32x2 %0, %1, %2;" : "=l"(d) : "l"(a), "l"(b));
    return d;
}
__device__ __forceinline__ unsigned long long pack2(float lo, float hi)
{
    unsigned long long d;
    asm("mov.b64 %0, {%1, %2};" : "=l"(d) : "f"(lo), "f"(hi));
    return d;
}
__device__ __forceinline__ float2 unpack2(unsigned long long v)
{
    float x, y;
    asm("mov.b64 {%0, %1}, %2;" : "=f"(x), "=f"(y) : "l"(v));
    return make_float2(x, y);
}

// ---------------------------------------------------------------------------
// Kernel 1: fused QKV projection.  out[m][e] = sum_d x[m][d] * W[e][d] + b[e]
// 64x64 tile, BK=32, f32x2 packed FMAs along k.
// ---------------------------------------------------------------------------
__global__ __launch_bounds__(256, 1)
void qkv_kernel(const float* __restrict__ x,
                const float* __restrict__ Wq, const float* __restrict__ bq,
                const float* __restrict__ Wk, const float* __restrict__ bk,
                const float* __restrict__ Wv, const float* __restrict__ bv)
{
    const int z = blockIdx.z;
    const float* W    = (z == 0) ? Wq : (z == 1) ? Wk : Wv;
    const float* bias = (z == 0) ? bq : (z == 1) ? bk : bv;
    float* out        = (z == 0) ? g_Q : (z == 1) ? g_K : g_V;

    const int e0 = blockIdx.x * 64;
    const int m0 = blockIdx.y * 64;
    const int t  = threadIdx.x;
    const int tx = t & 15, ty = t >> 4;

    __shared__ float Xs[64][36];
    __shared__ float Ws[64][36];

    unsigned long long acc2[4][4] = {};

    for (int k0 = 0; k0 < Dd; k0 += 32) {
        {
            int row = t >> 3;
            int col = (t & 7) * 4;
            #pragma unroll
            for (int rr = 0; rr < 2; rr++) {
                *(float4*)&Xs[row + rr*32][col] =
                    *(const float4*)&x[(size_t)(m0 + row + rr*32)*Dd + k0 + col];
                *(float4*)&Ws[row + rr*32][col] =
                    *(const float4*)&W[(size_t)(e0 + row + rr*32)*Dd + k0 + col];
            }
        }
        __syncthreads();
        #pragma unroll
        for (int kk = 0; kk < 32; kk += 4) {
            ulonglong2 a2[4], b2[4];
            #pragma unroll
            for (int i = 0; i < 4; i++)
                a2[i] = *(const ulonglong2*)&Xs[ty + i*16][kk];
            #pragma unroll
            for (int j = 0; j < 4; j++)
                b2[j] = *(const ulonglong2*)&Ws[tx + j*16][kk];
            #pragma unroll
            for (int i = 0; i < 4; i++)
                #pragma unroll
                for (int j = 0; j < 4; j++) {
                    acc2[i][j] = ffma2(a2[i].x, b2[j].x, acc2[i][j]);
                    acc2[i][j] = ffma2(a2[i].y, b2[j].y, acc2[i][j]);
                }
        }
        __syncthreads();
    }

    #pragma unroll
    for (int j = 0; j < 4; j++) {
        float bb = bias[e0 + tx + j*16];
        #pragma unroll
        for (int i = 0; i < 4; i++) {
            float2 v = unpack2(acc2[i][j]);
            out[(size_t)(m0 + ty + i*16)*Dd + e0 + tx + j*16] = v.x + v.y + bb;
        }
    }
}

// ---------------------------------------------------------------------------
// Kernel 2: flash-style attention, fp32 with packed f32x2 FMAs.
// One CTA per (batch, 64-query tile). 256 threads as 16x16.
// smem: Qs[64][256] | Ks[64][260] | Ps[64][68] | Vs[64][260] = 216,064 B
// Full K and V tiles resident per key-tile: 3 syncs per j0 (was 9).
// ---------------------------------------------------------------------------
#define QSD 256
#define KSD 260
#define VSD 260
#define PSD 68
#define SMEM_FLOATS (64*QSD + 64*KSD + 64*PSD + 64*VSD)
#define SMEM_BYTES  (SMEM_FLOATS * 4)

__global__ __launch_bounds__(256, 1)
void attn_kernel(const int* __restrict__ mask, float* __restrict__ out)
{
    extern __shared__ float sm[];
    float* Qs = sm;                    // 64 x 256
    float* Ks = Qs + 64*QSD;           // 64 x 260
    float* Ps = Ks + 64*KSD;           // 64 x 68
    float* Vs = Ps + 64*PSD;           // 64 x 260

    const int b  = blockIdx.y;
    const int q0 = blockIdx.x * 64;
    const int t  = threadIdx.x;
    const int tx = t & 15, ty = t >> 4;

    const float scale   = 0.0625f;                      // 1/sqrt(256)
    const float NEG_INF = __int_as_float(0xff800000);

    // Load Q tile (64 x 256), coalesced float4.
    #pragma unroll
    for (int it = 0; it < 16; it++) {
        int lin = it*1024 + t*4;
        int row = lin >> 8, col = lin & 255;
        *(float4*)&Qs[row*QSD + col] =
            *(const float4*)&g_Q[(size_t)(b*Nn + q0 + row)*Dd + col];
    }

    float m_i[4], l_i[4];
    unsigned long long o2[4][4][2] = {};  // [row i][col group jj][col pair]
    #pragma unroll
    for (int i = 0; i < 4; i++) { m_i[i] = NEG_INF; l_i[i] = 0.f; }

    for (int j0 = 0; j0 < Nn; j0 += 64) {
        __syncthreads();   // prior tile's Ps/Vs/Ks consumers done

        // ---- load full K and V tiles (64 x 256 each) ----
        #pragma unroll
        for (int it = 0; it < 16; it++) {
            int lin = it*1024 + t*4;
            int row = lin >> 8, col = lin & 255;
            *(float4*)&Ks[row*KSD + col] =
                *(const float4*)&g_K[(size_t)(b*Nn + j0 + row)*Dd + col];
            *(float4*)&Vs[row*VSD + col] =
                *(const float4*)&g_V[(size_t)(b*Nn + j0 + row)*Dd + col];
        }
        __syncthreads();

        // ---- S = Q @ K^T : one sync-free 64-iteration f32x2 stretch ----
        unsigned long long s2[4][4] = {};
        #pragma unroll 4
        for (int d = 0; d < Dd; d += 4) {
            ulonglong2 q2[4], k2[4];
            #pragma unroll
            for (int i = 0; i < 4; i++)
                q2[i] = *(const ulonglong2*)&Qs[(ty*4 + i)*QSD + d];
            #pragma unroll
            for (int j = 0; j < 4; j++)
                k2[j] = *(const ulonglong2*)&Ks[(tx + j*16)*KSD + d];
            #pragma unroll
            for (int i = 0; i < 4; i++)
                #pragma unroll
                for (int j = 0; j < 4; j++) {
                    s2[i][j] = ffma2(q2[i].x, k2[j].x, s2[i][j]);
                    s2[i][j] = ffma2(q2[i].y, k2[j].y, s2[i][j]);
                }
        }
        float s[4][4];
        #pragma unroll
        for (int i = 0; i < 4; i++)
            #pragma unroll
            for (int j = 0; j < 4; j++) {
                float2 v = unpack2(s2[i][j]);
                s[i][j] = v.x + v.y;
            }

        // ---- mask (fill BEFORE scaling, matching reference) ----
        #pragma unroll
        for (int i = 0; i < 4; i++) {
            const int* mrow = mask + ((size_t)(b*Nn + q0 + ty*4 + i))*(size_t)Nn + j0;
            #pragma unroll
            for (int j = 0; j < 4; j++) {
                int mv = mrow[tx + j*16];
                s[i][j] = (mv == 0) ? NEG_INF : s[i][j] * scale;
            }
        }

        // ---- online softmax (row stats across the 16-lane tx group) ----
        float p[4][4];
        #pragma unroll
        for (int i = 0; i < 4; i++) {
            float tmax = fmaxf(fmaxf(s[i][0], s[i][1]), fmaxf(s[i][2], s[i][3]));
            #pragma unroll
            for (int w = 8; w >= 1; w >>= 1)
                tmax = fmaxf(tmax, __shfl_xor_sync(0xffffffffu, tmax, w));
            float m_new = fmaxf(m_i[i], tmax);
            float alpha = __expf(m_i[i] - m_new);
            m_i[i] = m_new;
            float psum = 0.f;
            #pragma unroll
            for (int j = 0; j < 4; j++) {
                p[i][j] = __expf(s[i][j] - m_new);
                psum += p[i][j];
            }
            l_i[i] = l_i[i]*alpha + psum;   // lane-partial; reduced at end
            unsigned long long a2 = pack2(alpha, alpha);
            #pragma unroll
            for (int jj = 0; jj < 4; jj++) {
                o2[i][jj][0] = fmul2(o2[i][jj][0], a2);
                o2[i][jj][1] = fmul2(o2[i][jj][1], a2);
            }
        }

        // ---- stage P ----
        #pragma unroll
        for (int i = 0; i < 4; i++)
            #pragma unroll
            for (int j = 0; j < 4; j++)
                Ps[(ty*4 + i)*PSD + tx + j*16] = p[i][j];
        __syncthreads();

        // ---- O += P @ V (f32x2 packed along output columns) ----
        #pragma unroll 2
        for (int k0 = 0; k0 < 64; k0 += 4) {
            float4 p4[4];
            #pragma unroll
            for (int i = 0; i < 4; i++)
                p4[i] = *(const float4*)&Ps[(ty*4 + i)*PSD + k0];
            #pragma unroll
            for (int kk = 0; kk < 4; kk++) {
                unsigned long long pp[4];
                pp[0] = pack2(((const float*)&p4[0])[kk], ((const float*)&p4[0])[kk]);
                pp[1] = pack2(((const float*)&p4[1])[kk], ((const float*)&p4[1])[kk]);
                pp[2] = pack2(((const float*)&p4[2])[kk], ((const float*)&p4[2])[kk]);
                pp[3] = pack2(((const float*)&p4[3])[kk], ((const float*)&p4[3])[kk]);
                #pragma unroll
                for (int jj = 0; jj < 4; jj++) {
                    ulonglong2 v2 = *(const ulonglong2*)&Vs[(k0 + kk)*VSD + jj*64 + tx*4];
                    #pragma unroll
                    for (int i = 0; i < 4; i++) {
                        o2[i][jj][0] = ffma2(pp[i], v2.x, o2[i][jj][0]);
                        o2[i][jj][1] = ffma2(pp[i], v2.y, o2[i][jj][1]);
                    }
                }
            }
        }
        // next iteration's leading __syncthreads fences smem reuse
    }

    // ---- finalize: reduce l over the 16-lane group, scale, store ----
    #pragma unroll
    for (int i = 0; i < 4; i++) {
        float l = l_i[i];
        #pragma unroll
        for (int w = 8; w >= 1; w >>= 1)
            l += __shfl_xor_sync(0xffffffffu, l, w);
        float inv = 1.0f / l;
        int q = q0 + ty*4 + i;
        #pragma unroll
        for (int jj = 0; jj < 4; jj++) {
            float2 e0 = unpack2(o2[i][jj][0]);
            float2 e1 = unpack2(o2[i][jj][1]);
            float4 r;
            r.x = e0.x*inv; r.y = e0.y*inv;
            r.z = e1.x*inv; r.w = e1.y*inv;
            *(float4*)&out[(size_t)(b*Nn + q)*Dd + jj*64 + tx*4] = r;
        }
    }
}

// ---------------------------------------------------------------------------
// Launch. Inputs per metadata order: x, mask, Wq, bq, Wk, bk, Wv, bv.
// ---------------------------------------------------------------------------
extern "C" void kernel_launch(void* const* d_in, const int* in_sizes, int n_in,
                              void* d_out, int out_size)
{
    const float* x    = (const float*)d_in[0];
    const int*   mask = (const int*)  d_in[1];
    const float* Wq   = (const float*)d_in[2];
    const float* bq   = (const float*)d_in[3];
    const float* Wk   = (const float*)d_in[4];
    const float* bk   = (const float*)d_in[5];
    const float* Wv   = (const float*)d_in[6];
    const float* bv   = (const float*)d_in[7];
    float* out = (float*)d_out;

    cudaFuncSetAttribute(attn_kernel,
                         cudaFuncAttributeMaxDynamicSharedMemorySize, SMEM_BYTES);

    dim3 g1(Dd/64, Mm/64, 3);          // (4, 256, 3)
    qkv_kernel<<<g1, 256>>>(x, Wq, bq, Wk, bk, Wv, bv);

    dim3 g2(Nn/64, Bb);                // (64, 4)
    attn_kernel<<<g2, 256, SMEM_BYTES>>>(mask, out);
}

// round 3
// speedup vs baseline: 2.2415x; 1.0024x over previous
#include <cuda_runtime.h>
#include <cstdint>

// Problem constants
#define Bb 4
#define Nn 4096
#define Dd 256
#define Mm (Bb*Nn)   // 16384 rows

// Scratch for Q, K, V projections (allocation-free: __device__ globals)
__device__ float g_Q[Bb*Nn*Dd];
__device__ float g_K[Bb*Nn*Dd];
__device__ float g_V[Bb*Nn*Dd];

// ---------------------------------------------------------------------------
// Packed f32x2 helpers (Blackwell FFMA2: 2 fp32 FMAs per instruction)
// ---------------------------------------------------------------------------
__device__ __forceinline__ unsigned long long ffma2(unsigned long long a,
                                                    unsigned long long b,
                                                    unsigned long long c)
{
    unsigned long long d;
    asm("fma.rn.f32x2 %0, %1, %2, %3;" : "=l"(d) : "l"(a), "l"(b), "l"(c));
    return d;
}
__device__ __forceinline__ unsigned long long fmul2(unsigned long long a,
                                                    unsigned long long b)
{
    unsigned long long d;
    asm("mul.rn.f32x2 %0, %1, %2;" : "=l"(d) : "l"(a), "l"(b));
    return d;
}
__device__ __forceinline__ unsigned long long pack2(float lo, float hi)
{
    unsigned long long d;
    asm("mov.b64 %0, {%1, %2};" : "=l"(d) : "f"(lo), "f"(hi));
    return d;
}
__device__ __forceinline__ float2 unpack2(unsigned long long v)
{
    float x, y;
    asm("mov.b64 {%0, %1}, %2;" : "=f"(x), "=f"(y) : "l"(v));
    return make_float2(x, y);
}

// ---------------------------------------------------------------------------
// Kernel 1: fused QKV projection.  out[m][e] = sum_d x[m][d] * W[e][d] + b[e]
// 64x64 tile, BK=32, f32x2 packed FMAs along k.
// ---------------------------------------------------------------------------
__global__ __launch_bounds__(256, 1)
void qkv_kernel(const float* __restrict__ x,
                const float* __restrict__ Wq, const float* __restrict__ bq,
                const float* __restrict__ Wk, const float* __restrict__ bk,
                const float* __restrict__ Wv, const float* __restrict__ bv)
{
    const int z = blockIdx.z;
    const float* W    = (z == 0) ? Wq : (z == 1) ? Wk : Wv;
    const float* bias = (z == 0) ? bq : (z == 1) ? bk : bv;
    float* out        = (z == 0) ? g_Q : (z == 1) ? g_K : g_V;

    const int e0 = blockIdx.x * 64;
    const int m0 = blockIdx.y * 64;
    const int t  = threadIdx.x;
    const int tx = t & 15, ty = t >> 4;

    __shared__ float Xs[64][36];
    __shared__ float Ws[64][36];

    unsigned long long acc2[4][4] = {};

    for (int k0 = 0; k0 < Dd; k0 += 32) {
        {
            int row = t >> 3;
            int col = (t & 7) * 4;
            #pragma unroll
            for (int rr = 0; rr < 2; rr++) {
                *(float4*)&Xs[row + rr*32][col] =
                    *(const float4*)&x[(size_t)(m0 + row + rr*32)*Dd + k0 + col];
                *(float4*)&Ws[row + rr*32][col] =
                    *(const float4*)&W[(size_t)(e0 + row + rr*32)*Dd + k0 + col];
            }
        }
        __syncthreads();
        #pragma unroll
        for (int kk = 0; kk < 32; kk += 4) {
            ulonglong2 a2[4], b2[4];
            #pragma unroll
            for (int i = 0; i < 4; i++)
                a2[i] = *(const ulonglong2*)&Xs[ty + i*16][kk];
            #pragma unroll
            for (int j = 0; j < 4; j++)
                b2[j] = *(const ulonglong2*)&Ws[tx + j*16][kk];
            #pragma unroll
            for (int i = 0; i < 4; i++)
                #pragma unroll
                for (int j = 0; j < 4; j++) {
                    acc2[i][j] = ffma2(a2[i].x, b2[j].x, acc2[i][j]);
                    acc2[i][j] = ffma2(a2[i].y, b2[j].y, acc2[i][j]);
                }
        }
        __syncthreads();
    }

    #pragma unroll
    for (int j = 0; j < 4; j++) {
        float bb = bias[e0 + tx + j*16];
        #pragma unroll
        for (int i = 0; i < 4; i++) {
            float2 v = unpack2(acc2[i][j]);
            out[(size_t)(m0 + ty + i*16)*Dd + e0 + tx + j*16] = v.x + v.y + bb;
        }
    }
}

// ---------------------------------------------------------------------------
// Kernel 2: flash-style attention, fp32 with packed f32x2 FMAs.
// One CTA per (batch, 64-query tile). 256 threads as 16x16.
// smem: Qs[64][256] | Ks[64][260] | Ps[64][68] | Vs[64][260] = 216,064 B
// Full K and V tiles resident per key-tile: 3 syncs per j0 (was 9).
// ---------------------------------------------------------------------------
#define QSD 256
#define KSD 260
#define VSD 260
#define PSD 68
#define SMEM_FLOATS (64*QSD + 64*KSD + 64*PSD + 64*VSD)
#define SMEM_BYTES  (SMEM_FLOATS * 4)

__global__ __launch_bounds__(256, 1)
void attn_kernel(const int* __restrict__ mask, float* __restrict__ out)
{
    extern __shared__ float sm[];
    float* Qs = sm;                    // 64 x 256
    float* Ks = Qs + 64*QSD;           // 64 x 260
    float* Ps = Ks + 64*KSD;           // 64 x 68
    float* Vs = Ps + 64*PSD;           // 64 x 260

    const int b  = blockIdx.y;
    const int q0 = blockIdx.x * 64;
    const int t  = threadIdx.x;
    const int tx = t & 15, ty = t >> 4;

    const float scale   = 0.0625f;                      // 1/sqrt(256)
    const float NEG_INF = __int_as_float(0xff800000);

    // Load Q tile (64 x 256), coalesced float4.
    #pragma unroll
    for (int it = 0; it < 16; it++) {
        int lin = it*1024 + t*4;
        int row = lin >> 8, col = lin & 255;
        *(float4*)&Qs[row*QSD + col] =
            *(const float4*)&g_Q[(size_t)(b*Nn + q0 + row)*Dd + col];
    }

    float m_i[4], l_i[4];
    unsigned long long o2[4][4][2] = {};  // [row i][col group jj][col pair]
    #pragma unroll
    for (int i = 0; i < 4; i++) { m_i[i] = NEG_INF; l_i[i] = 0.f; }

    for (int j0 = 0; j0 < Nn; j0 += 64) {
        __syncthreads();   // prior tile's Ps/Vs/Ks consumers done

        // ---- load full K and V tiles (64 x 256 each) ----
        #pragma unroll
        for (int it = 0; it < 16; it++) {
            int lin = it*1024 + t*4;
            int row = lin >> 8, col = lin & 255;
            *(float4*)&Ks[row*KSD + col] =
                *(const float4*)&g_K[(size_t)(b*Nn + j0 + row)*Dd + col];
            *(float4*)&Vs[row*VSD + col] =
                *(const float4*)&g_V[(size_t)(b*Nn + j0 + row)*Dd + col];
        }
        __syncthreads();

        // ---- S = Q @ K^T : one sync-free 64-iteration f32x2 stretch ----
        unsigned long long s2[4][4] = {};
        #pragma unroll 4
        for (int d = 0; d < Dd; d += 4) {
            ulonglong2 q2[4], k2[4];
            #pragma unroll
            for (int i = 0; i < 4; i++)
                q2[i] = *(const ulonglong2*)&Qs[(ty*4 + i)*QSD + d];
            #pragma unroll
            for (int j = 0; j < 4; j++)
                k2[j] = *(const ulonglong2*)&Ks[(tx + j*16)*KSD + d];
            #pragma unroll
            for (int i = 0; i < 4; i++)
                #pragma unroll
                for (int j = 0; j < 4; j++) {
                    s2[i][j] = ffma2(q2[i].x, k2[j].x, s2[i][j]);
                    s2[i][j] = ffma2(q2[i].y, k2[j].y, s2[i][j]);
                }
        }
        float s[4][4];
        #pragma unroll
        for (int i = 0; i < 4; i++)
            #pragma unroll
            for (int j = 0; j < 4; j++) {
                float2 v = unpack2(s2[i][j]);
                s[i][j] = v.x + v.y;
            }

        // ---- mask (fill BEFORE scaling, matching reference) ----
        #pragma unroll
        for (int i = 0; i < 4; i++) {
            const int* mrow = mask + ((size_t)(b*Nn + q0 + ty*4 + i))*(size_t)Nn + j0;
            #pragma unroll
            for (int j = 0; j < 4; j++) {
                int mv = mrow[tx + j*16];
                s[i][j] = (mv == 0) ? NEG_INF : s[i][j] * scale;
            }
        }

        // ---- online softmax (row stats across the 16-lane tx group) ----
        float p[4][4];
        #pragma unroll
        for (int i = 0; i < 4; i++) {
            float tmax = fmaxf(fmaxf(s[i][0], s[i][1]), fmaxf(s[i][2], s[i][3]));
            #pragma unroll
            for (int w = 8; w >= 1; w >>= 1)
                tmax = fmaxf(tmax, __shfl_xor_sync(0xffffffffu, tmax, w));
            float m_new = fmaxf(m_i[i], tmax);
            float alpha = __expf(m_i[i] - m_new);
            m_i[i] = m_new;
            float psum = 0.f;
            #pragma unroll
            for (int j = 0; j < 4; j++) {
                p[i][j] = __expf(s[i][j] - m_new);
                psum += p[i][j];
            }
            l_i[i] = l_i[i]*alpha + psum;   // lane-partial; reduced at end
            unsigned long long a2 = pack2(alpha, alpha);
            #pragma unroll
            for (int jj = 0; jj < 4; jj++) {
                o2[i][jj][0] = fmul2(o2[i][jj][0], a2);
                o2[i][jj][1] = fmul2(o2[i][jj][1], a2);
            }
        }

        // ---- stage P ----
        #pragma unroll
        for (int i = 0; i < 4; i++)
            #pragma unroll
            for (int j = 0; j < 4; j++)
                Ps[(ty*4 + i)*PSD + tx + j*16] = p[i][j];
        __syncthreads();

        // ---- O += P @ V (f32x2 packed along output columns) ----
        #pragma unroll 2
        for (int k0 = 0; k0 < 64; k0 += 4) {
            float4 p4[4];
            #pragma unroll
            for (int i = 0; i < 4; i++)
                p4[i] = *(const float4*)&Ps[(ty*4 + i)*PSD + k0];
            #pragma unroll
            for (int kk = 0; kk < 4; kk++) {
                unsigned long long pp[4];
                pp[0] = pack2(((const float*)&p4[0])[kk], ((const float*)&p4[0])[kk]);
                pp[1] = pack2(((const float*)&p4[1])[kk], ((const float*)&p4[1])[kk]);
                pp[2] = pack2(((const float*)&p4[2])[kk], ((const float*)&p4[2])[kk]);
                pp[3] = pack2(((const float*)&p4[3])[kk], ((const float*)&p4[3])[kk]);
                #pragma unroll
                for (int jj = 0; jj < 4; jj++) {
                    ulonglong2 v2 = *(const ulonglong2*)&Vs[(k0 + kk)*VSD + jj*64 + tx*4];
                    #pragma unroll
                    for (int i = 0; i < 4; i++) {
                        o2[i][jj][0] = ffma2(pp[i], v2.x, o2[i][jj][0]);
                        o2[i][jj][1] = ffma2(pp[i], v2.y, o2[i][jj][1]);
                    }
                }
            }
        }
        // next iteration's leading __syncthreads fences smem reuse
    }

    // ---- finalize: reduce l over the 16-lane group, scale, store ----
    #pragma unroll
    for (int i = 0; i < 4; i++) {
        float l = l_i[i];
        #pragma unroll
        for (int w = 8; w >= 1; w >>= 1)
            l += __shfl_xor_sync(0xffffffffu, l, w);
        float inv = 1.0f / l;
        int q = q0 + ty*4 + i;
        #pragma unroll
        for (int jj = 0; jj < 4; jj++) {
            float2 e0 = unpack2(o2[i][jj][0]);
            float2 e1 = unpack2(o2[i][jj][1]);
            float4 r;
            r.x = e0.x*inv; r.y = e0.y*inv;
            r.z = e1.x*inv; r.w = e1.y*inv;
            *(float4*)&out[(size_t)(b*Nn + q)*Dd + jj*64 + tx*4] = r;
        }
    }
}

// ---------------------------------------------------------------------------
// Launch. Inputs per metadata order: x, mask, Wq, bq, Wk, bk, Wv, bv.
// ---------------------------------------------------------------------------
extern "C" void kernel_launch(void* const* d_in, const int* in_sizes, int n_in,
                              void* d_out, int out_size)
{
    const float* x    = (const float*)d_in[0];
    const int*   mask = (const int*)  d_in[1];
    const float* Wq   = (const float*)d_in[2];
    const float* bq   = (const float*)d_in[3];
    const float* Wk   = (const float*)d_in[4];
    const float* bk   = (const float*)d_in[5];
    const float* Wv   = (const float*)d_in[6];
    const float* bv   = (const float*)d_in[7];
    float* out = (float*)d_out;

    cudaFuncSetAttribute(attn_kernel,
                         cudaFuncAttributeMaxDynamicSharedMemorySize, SMEM_BYTES);

    dim3 g1(Dd/64, Mm/64, 3);          // (4, 256, 3)
    qkv_kernel<<<g1, 256>>>(x, Wq, bq, Wk, bk, Wv, bv);

    dim3 g2(Nn/64, Bb);                // (64, 4)
    attn_kernel<<<g2, 256, SMEM_BYTES>>>(mask, out);
}